// round 2
// baseline (speedup 1.0000x reference)
#include <cuda_runtime.h>

// Problem constants (shapes fixed by the dataset)
#define NMAX   50000
#define IN_DIM 128      // in_dim
#define HD     8        // heads
#define RR     16       // hidden rank
#define DD     16       // out dim per head
// H*R = H*D = 128 columns for every projection

// Scratch: __device__ globals (no runtime allocation allowed)
__device__ float g_K[NMAX * 128];   // h @ q
__device__ float g_Q[NMAX * 128];   // h @ p
__device__ float g_V[NMAX * 128];   // h @ Wv
__device__ float g_z[NMAX * HD];    // softmax denominators

// ---------------------------------------------------------------------------
// Zero accumulators (d_out is poisoned to 0xAA by the harness)
// ---------------------------------------------------------------------------
__global__ void zero_kernel(float* __restrict__ out, int n_nodes) {
    int i = blockIdx.x * blockDim.x + threadIdx.x;
    if (i < n_nodes * 128) out[i] = 0.0f;
    if (i < n_nodes * HD)  g_z[i] = 0.0f;
}

// ---------------------------------------------------------------------------
// Fused projection GEMM: out[n, c] = sum_k h[n,k] * W[k,c]
// Tile: 64 nodes x 128 cols per block; thread tile 8 nodes x 4 cols.
// blockIdx.y selects which of the 3 projections this block computes.
// ---------------------------------------------------------------------------
__global__ __launch_bounds__(256) void gemm_kernel(
    const float* __restrict__ h,
    const float* __restrict__ wK,   // q  -> g_K
    const float* __restrict__ wQ,   // p  -> g_Q
    const float* __restrict__ wV,   // Wv -> g_V
    int n_nodes)
{
    __shared__ float sh_h[64][36];    // padded: avoids STS.128 bank conflicts
    __shared__ float sh_w[32][128];

    const float* w    = (blockIdx.y == 0) ? wK : (blockIdx.y == 1 ? wQ : wV);
    float*       outp = (blockIdx.y == 0) ? g_K : (blockIdx.y == 1 ? g_Q : g_V);

    const int nb  = blockIdx.x * 64;
    const int tid = threadIdx.x;
    const int tx  = tid & 31;         // col group: cols tx*4 .. tx*4+3
    const int ty  = tid >> 5;         // node group: nodes ty*8 .. ty*8+7

    float4 acc[8];
#pragma unroll
    for (int n = 0; n < 8; ++n) acc[n] = make_float4(0.f, 0.f, 0.f, 0.f);

    const float4* h4 = (const float4*)h;  // row stride 32 float4
    const float4* w4 = (const float4*)w;

    for (int kc = 0; kc < 4; ++kc) {      // K chunks of 32
        __syncthreads();
        // stage h chunk: 64 nodes x 32 k  (512 float4)
#pragma unroll
        for (int i = 0; i < 2; ++i) {
            int f    = tid + i * 256;
            int node = f >> 3, k4 = f & 7;
            int row  = nb + node;
            if (row >= n_nodes) row = n_nodes - 1;   // clamp; discarded on store
            *(float4*)&sh_h[node][k4 * 4] = h4[row * 32 + kc * 8 + k4];
        }
        // stage W chunk: 32 k x 128 cols (1024 float4)
#pragma unroll
        for (int i = 0; i < 4; ++i) {
            int f = tid + i * 256;
            int r = f >> 5, c4 = f & 31;
            *(float4*)&sh_w[r][c4 * 4] = w4[(kc * 32 + r) * 32 + c4];
        }
        __syncthreads();

#pragma unroll 8
        for (int k = 0; k < 32; ++k) {
            float4 wv4 = *(const float4*)&sh_w[k][tx * 4];
#pragma unroll
            for (int n = 0; n < 8; ++n) {
                float hv = sh_h[ty * 8 + n][k];
                acc[n].x += hv * wv4.x;
                acc[n].y += hv * wv4.y;
                acc[n].z += hv * wv4.z;
                acc[n].w += hv * wv4.w;
            }
        }
    }

    float4* o4 = (float4*)outp;
#pragma unroll
    for (int n = 0; n < 8; ++n) {
        int row = nb + ty * 8 + n;
        if (row < n_nodes) o4[row * 32 + tx] = acc[n];
    }
}

// ---------------------------------------------------------------------------
// Edge phase: one warp per edge.
// lane l: head = l>>2, covers r/d = (l&3)*4 .. +3 via float4.
// score_h = exp(clip(dot(K[src,h,:], Q[dst,h,:]) / 4, -5, 5))
// wV[dst] += V[src] * score  (vector red.global.add.v4.f32)
// z[dst]  += score
// ---------------------------------------------------------------------------
__global__ __launch_bounds__(256) void edge_kernel(
    const int* __restrict__ src, const int* __restrict__ dst,
    float* __restrict__ wv_out, int n_edges)
{
    int gw = (int)((blockIdx.x * 256u + threadIdx.x) >> 5);
    if (gw >= n_edges) return;
    int lane = threadIdx.x & 31;

    int s = __ldg(&src[gw]);
    int d = __ldg(&dst[gw]);

    float4 k4 = ((const float4*)g_K)[s * 32 + lane];
    float4 q4 = ((const float4*)g_Q)[d * 32 + lane];
    float dot = k4.x * q4.x + k4.y * q4.y + k4.z * q4.z + k4.w * q4.w;
    // reduce the 4 lanes of this head's quad
    dot += __shfl_xor_sync(0xffffffffu, dot, 1);
    dot += __shfl_xor_sync(0xffffffffu, dot, 2);

    float sc    = fminf(fmaxf(dot * 0.25f, -5.0f), 5.0f);  // SCALE = sqrt(16) = 4
    float score = __expf(sc);

    float4 v4 = ((const float4*)g_V)[s * 32 + lane];
    float* addr = wv_out + d * 128 + lane * 4;
    asm volatile("red.global.add.v4.f32 [%0], {%1,%2,%3,%4};"
                 :: "l"(addr),
                    "f"(v4.x * score), "f"(v4.y * score),
                    "f"(v4.z * score), "f"(v4.w * score)
                 : "memory");

    if ((lane & 3) == 0)
        atomicAdd(&g_z[d * HD + (lane >> 2)], score);
}

// ---------------------------------------------------------------------------
// Final: out = wV / z, with z==0 -> 0.001
// ---------------------------------------------------------------------------
__global__ void final_kernel(float* __restrict__ out, int n_nodes) {
    int i = blockIdx.x * blockDim.x + threadIdx.x;
    if (i >= n_nodes * 128) return;
    float z = g_z[i >> 4];          // i = n*128 + h*16 + d  ->  i>>4 = n*8 + h
    if (z == 0.0f) z = 0.001f;
    out[i] = out[i] / z;
}

// ---------------------------------------------------------------------------
// kernel_launch — graph-capturable, allocation-free
// Inputs (metadata order): h[N*128] f32, src[E] i32, dst[E] i32,
//                          p[128*128] f32, q[128*128] f32, Wv[128*128] f32
// Output: [N, 8, 16] f32
// ---------------------------------------------------------------------------
extern "C" void kernel_launch(void* const* d_in, const int* in_sizes, int n_in,
                              void* d_out, int out_size) {
    const float* h   = (const float*)d_in[0];
    const int*   src = (const int*)  d_in[1];
    const int*   dst = (const int*)  d_in[2];
    const float* p   = (const float*)d_in[3];
    const float* q   = (const float*)d_in[4];
    const float* wv  = (const float*)d_in[5];

    int n_nodes = in_sizes[0] / IN_DIM;   // 50000
    int n_edges = in_sizes[1];            // 1.6M

    float* out = (float*)d_out;

    // 1. zero accumulators
    {
        int total  = n_nodes * 128;
        int blocks = (total + 255) / 256;
        zero_kernel<<<blocks, 256>>>(out, n_nodes);
    }
    // 2. projections K = h@q, Q = h@p, V = h@Wv
    {
        dim3 grid((n_nodes + 63) / 64, 3);
        gemm_kernel<<<grid, 256>>>(h, q, p, wv, n_nodes);
    }
    // 3. edge scatter (warp per edge)
    {
        long long warps  = n_edges;
        int       blocks = (int)((warps * 32 + 255) / 256);
        edge_kernel<<<blocks, 256>>>(src, dst, out, n_edges);
    }
    // 4. normalize
    {
        int total  = n_nodes * 128;
        int blocks = (total + 255) / 256;
        final_kernel<<<blocks, 256>>>(out, n_nodes);
    }
}

// round 6
// speedup vs baseline: 1.3224x; 1.3224x over previous
#include <cuda_runtime.h>

#define NMAX   50000
#define EMAX   1700000
#define IN_DIM 128
#define HD     8
#define RR     16
#define DD     16

// Scratch (__device__ globals; no runtime allocation allowed)
__device__ float g_K[NMAX * 128];     // h @ q
__device__ float g_Q[NMAX * 128];     // h @ p
__device__ float g_V[NMAX * 128];     // h @ Wv
__device__ int   g_deg[NMAX];
__device__ int   g_start[NMAX + 1];   // exclusive prefix of degrees
__device__ int   g_cursor[NMAX];
__device__ int   g_esrc[EMAX];        // src node per edge, bucketed by dst

// ---------------------------------------------------------------------------
// CSR build step 1: zero degree counters
// ---------------------------------------------------------------------------
__global__ void zero_deg_kernel(int n_nodes) {
    int i = blockIdx.x * blockDim.x + threadIdx.x;
    if (i < n_nodes) g_deg[i] = 0;
}

// step 2: histogram of dst
__global__ void count_kernel(const int* __restrict__ dst, int n_edges) {
    int e = blockIdx.x * blockDim.x + threadIdx.x;
    if (e < n_edges) atomicAdd(&g_deg[dst[e]], 1);
}

// step 3: exclusive scan (single block, 1024 threads, sequential chunks)
__global__ __launch_bounds__(1024) void scan_kernel(int n_nodes) {
    __shared__ int warp_sums[32];
    __shared__ int carry_s;
    const int tid  = threadIdx.x;
    const int lane = tid & 31;
    const int wid  = tid >> 5;
    if (tid == 0) carry_s = 0;
    __syncthreads();

    for (int base = 0; base < n_nodes; base += 1024) {
        int i = base + tid;
        int v = (i < n_nodes) ? g_deg[i] : 0;
        // intra-warp inclusive scan
        int x = v;
#pragma unroll
        for (int o = 1; o < 32; o <<= 1) {
            int t = __shfl_up_sync(0xffffffffu, x, o);
            if (lane >= o) x += t;
        }
        if (lane == 31) warp_sums[wid] = x;
        __syncthreads();
        if (wid == 0) {
            int s = warp_sums[lane];
#pragma unroll
            for (int o = 1; o < 32; o <<= 1) {
                int t = __shfl_up_sync(0xffffffffu, s, o);
                if (lane >= o) s += t;
            }
            warp_sums[lane] = s;
        }
        __syncthreads();
        int incl = x + (wid > 0 ? warp_sums[wid - 1] : 0) + carry_s;
        if (i < n_nodes) {
            g_start[i]  = incl - v;
            g_cursor[i] = incl - v;
        }
        __syncthreads();
        if (tid == 0) carry_s += warp_sums[31];
        __syncthreads();
    }
    if (tid == 0) g_start[n_nodes] = carry_s;
}

// step 4: scatter src indices into dst buckets
__global__ void scatter_kernel(const int* __restrict__ src,
                               const int* __restrict__ dst, int n_edges) {
    int e = blockIdx.x * blockDim.x + threadIdx.x;
    if (e >= n_edges) return;
    int slot = atomicAdd(&g_cursor[dst[e]], 1);
    g_esrc[slot] = src[e];
}

// ---------------------------------------------------------------------------
// Projection GEMM: out[n,c] = sum_k h[n,k] * W[k,c]
// 64 nodes x 128 cols per block; thread tile 8x4; blockIdx.y picks projection.
// ---------------------------------------------------------------------------
__global__ __launch_bounds__(256) void gemm_kernel(
    const float* __restrict__ h,
    const float* __restrict__ wK,
    const float* __restrict__ wQ,
    const float* __restrict__ wV,
    int n_nodes)
{
    __shared__ float sh_h[64][36];
    __shared__ float sh_w[32][128];

    const float* w    = (blockIdx.y == 0) ? wK : (blockIdx.y == 1 ? wQ : wV);
    float*       outp = (blockIdx.y == 0) ? g_K : (blockIdx.y == 1 ? g_Q : g_V);

    const int nb  = blockIdx.x * 64;
    const int tid = threadIdx.x;
    const int tx  = tid & 31;
    const int ty  = tid >> 5;

    float4 acc[8];
#pragma unroll
    for (int n = 0; n < 8; ++n) acc[n] = make_float4(0.f, 0.f, 0.f, 0.f);

    const float4* h4 = (const float4*)h;
    const float4* w4 = (const float4*)w;

    for (int kc = 0; kc < 4; ++kc) {
        __syncthreads();
#pragma unroll
        for (int i = 0; i < 2; ++i) {
            int f    = tid + i * 256;
            int node = f >> 3, k4 = f & 7;
            int row  = nb + node;
            if (row >= n_nodes) row = n_nodes - 1;
            *(float4*)&sh_h[node][k4 * 4] = h4[row * 32 + kc * 8 + k4];
        }
#pragma unroll
        for (int i = 0; i < 4; ++i) {
            int f = tid + i * 256;
            int r = f >> 5, c4 = f & 31;
            *(float4*)&sh_w[r][c4 * 4] = w4[(kc * 32 + r) * 32 + c4];
        }
        __syncthreads();

#pragma unroll 8
        for (int k = 0; k < 32; ++k) {
            float4 wv4 = *(const float4*)&sh_w[k][tx * 4];
#pragma unroll
            for (int n = 0; n < 8; ++n) {
                float hv = sh_h[ty * 8 + n][k];
                acc[n].x += hv * wv4.x;
                acc[n].y += hv * wv4.y;
                acc[n].z += hv * wv4.z;
                acc[n].w += hv * wv4.w;
            }
        }
    }

    float4* o4 = (float4*)outp;
#pragma unroll
    for (int n = 0; n < 8; ++n) {
        int row = nb + ty * 8 + n;
        if (row < n_nodes) o4[row * 32 + tx] = acc[n];
    }
}

// ---------------------------------------------------------------------------
// Gather: one warp per dst node. lane l -> head l>>2, elems (l&3)*4..+3.
// Q[dst] held in registers; registers accumulate wV and z; single store
// with the z-normalization fused in. No atomics.
// ---------------------------------------------------------------------------
__global__ __launch_bounds__(256) void gather_kernel(
    float* __restrict__ out, int n_nodes)
{
    const int warp = (int)((blockIdx.x * 256u + threadIdx.x) >> 5);
    if (warp >= n_nodes) return;
    const int lane = threadIdx.x & 31;
    const int node = warp;

    const float4* K4 = (const float4*)g_K;
    const float4* Q4 = (const float4*)g_Q;
    const float4* V4 = (const float4*)g_V;

    const float4 q4 = Q4[node * 32 + lane];

    const int beg = g_start[node];
    const int end = g_start[node + 1];

    float4 acc = make_float4(0.f, 0.f, 0.f, 0.f);
    float  zacc = 0.f;

    for (int base = beg; base < end; base += 32) {
        const int cnt  = min(32, end - base);
        const int myidx = (base + lane < end) ? __ldg(&g_esrc[base + lane]) : 0;

        if (cnt == 32) {
#pragma unroll 4
            for (int i = 0; i < 32; ++i) {
                int s = __shfl_sync(0xffffffffu, myidx, i);
                float4 k4 = K4[s * 32 + lane];
                float dot = k4.x * q4.x + k4.y * q4.y + k4.z * q4.z + k4.w * q4.w;
                dot += __shfl_xor_sync(0xffffffffu, dot, 1);
                dot += __shfl_xor_sync(0xffffffffu, dot, 2);
                float sc    = fminf(fmaxf(dot * 0.25f, -5.0f), 5.0f);
                float score = __expf(sc);
                float4 v4 = V4[s * 32 + lane];
                acc.x += v4.x * score;
                acc.y += v4.y * score;
                acc.z += v4.z * score;
                acc.w += v4.w * score;
                zacc  += score;
            }
        } else {
            for (int i = 0; i < cnt; ++i) {
                int s = __shfl_sync(0xffffffffu, myidx, i);
                float4 k4 = K4[s * 32 + lane];
                float dot = k4.x * q4.x + k4.y * q4.y + k4.z * q4.z + k4.w * q4.w;
                dot += __shfl_xor_sync(0xffffffffu, dot, 1);
                dot += __shfl_xor_sync(0xffffffffu, dot, 2);
                float sc    = fminf(fmaxf(dot * 0.25f, -5.0f), 5.0f);
                float score = __expf(sc);
                float4 v4 = V4[s * 32 + lane];
                acc.x += v4.x * score;
                acc.y += v4.y * score;
                acc.z += v4.z * score;
                acc.w += v4.w * score;
                zacc  += score;
            }
        }
    }

    float z = (zacc == 0.0f) ? 0.001f : zacc;
    float inv = 1.0f / z;
    float4 r = make_float4(acc.x * inv, acc.y * inv, acc.z * inv, acc.w * inv);
    ((float4*)out)[node * 32 + lane] = r;
}

// ---------------------------------------------------------------------------
// kernel_launch — graph-capturable, allocation-free
// Inputs: h[N*128] f32, src[E] i32, dst[E] i32,
//         p[128*128] f32, q[128*128] f32, Wv[128*128] f32
// Output: [N, 8, 16] f32
// ---------------------------------------------------------------------------
extern "C" void kernel_launch(void* const* d_in, const int* in_sizes, int n_in,
                              void* d_out, int out_size) {
    const float* h   = (const float*)d_in[0];
    const int*   src = (const int*)  d_in[1];
    const int*   dst = (const int*)  d_in[2];
    const float* p   = (const float*)d_in[3];
    const float* q   = (const float*)d_in[4];
    const float* wv  = (const float*)d_in[5];

    int n_nodes = in_sizes[0] / IN_DIM;
    int n_edges = in_sizes[1];

    float* out = (float*)d_out;

    // CSR build (dst-bucketed src lists)
    zero_deg_kernel<<<(n_nodes + 255) / 256, 256>>>(n_nodes);
    count_kernel<<<(n_edges + 255) / 256, 256>>>(dst, n_edges);
    scan_kernel<<<1, 1024>>>(n_nodes);
    scatter_kernel<<<(n_edges + 255) / 256, 256>>>(src, dst, n_edges);

    // Projections K = h@q, Q = h@p, V = h@Wv
    {
        dim3 grid((n_nodes + 63) / 64, 3);
        gemm_kernel<<<grid, 256>>>(h, q, p, wv, n_nodes);
    }

    // Per-node gather + fused normalize
    {
        int warps_per_block = 8;
        int blocks = (n_nodes + warps_per_block - 1) / warps_per_block;
        gather_kernel<<<blocks, 256>>>(out, n_nodes);
    }
}

// round 8
// speedup vs baseline: 1.4557x; 1.1008x over previous
#include <cuda_runtime.h>
#include <cstdint>

#define NMAX   50000
#define EMAX   1700000
#define IN_DIM 128
#define HD     8

// Scratch (__device__ globals; no runtime allocation allowed)
__device__ float g_K[NMAX * 128];     // h @ q
__device__ float g_Q[NMAX * 128];     // h @ p
__device__ float g_V[NMAX * 128];     // h @ Wv
__device__ int   g_deg[NMAX];
__device__ int   g_start[NMAX + 1];
__device__ int   g_cursor[NMAX];
__device__ int   g_esrc[EMAX];

// ---------------------------------------------------------------------------
// f32x2 packed-math helpers (PTX .f32x2: family-wide sm_100+, base target OK)
// ---------------------------------------------------------------------------
__device__ __forceinline__ unsigned long long pack2(float a, float b) {
    unsigned long long r;
    asm("mov.b64 %0, {%1, %2};" : "=l"(r) : "f"(a), "f"(b));
    return r;
}
__device__ __forceinline__ unsigned long long ffma2(unsigned long long a,
                                                    unsigned long long b,
                                                    unsigned long long c) {
    unsigned long long d;
    asm("fma.rn.f32x2 %0, %1, %2, %3;" : "=l"(d) : "l"(a), "l"(b), "l"(c));
    return d;
}
__device__ __forceinline__ void unpack2(unsigned long long v, float& lo, float& hi) {
    asm("mov.b64 {%0, %1}, %2;" : "=f"(lo), "=f"(hi) : "l"(v));
}

// ---------------------------------------------------------------------------
// CSR build
// ---------------------------------------------------------------------------
__global__ void zero_deg_kernel(int n_nodes) {
    int i = blockIdx.x * blockDim.x + threadIdx.x;
    if (i < n_nodes) g_deg[i] = 0;
}
__global__ void count_kernel(const int* __restrict__ dst, int n_edges) {
    int e = blockIdx.x * blockDim.x + threadIdx.x;
    if (e < n_edges) atomicAdd(&g_deg[dst[e]], 1);
}
__global__ __launch_bounds__(1024) void scan_kernel(int n_nodes) {
    __shared__ int warp_sums[32];
    __shared__ int carry_s;
    const int tid  = threadIdx.x;
    const int lane = tid & 31;
    const int wid  = tid >> 5;
    if (tid == 0) carry_s = 0;
    __syncthreads();
    for (int base = 0; base < n_nodes; base += 1024) {
        int i = base + tid;
        int v = (i < n_nodes) ? g_deg[i] : 0;
        int x = v;
#pragma unroll
        for (int o = 1; o < 32; o <<= 1) {
            int t = __shfl_up_sync(0xffffffffu, x, o);
            if (lane >= o) x += t;
        }
        if (lane == 31) warp_sums[wid] = x;
        __syncthreads();
        if (wid == 0) {
            int s = warp_sums[lane];
#pragma unroll
            for (int o = 1; o < 32; o <<= 1) {
                int t = __shfl_up_sync(0xffffffffu, s, o);
                if (lane >= o) s += t;
            }
            warp_sums[lane] = s;
        }
        __syncthreads();
        int incl = x + (wid > 0 ? warp_sums[wid - 1] : 0) + carry_s;
        if (i < n_nodes) {
            g_start[i]  = incl - v;
            g_cursor[i] = incl - v;
        }
        __syncthreads();
        if (tid == 0) carry_s += warp_sums[31];
        __syncthreads();
    }
    if (tid == 0) g_start[n_nodes] = carry_s;
}
__global__ void scatter_kernel(const int* __restrict__ src,
                               const int* __restrict__ dst, int n_edges) {
    int e = blockIdx.x * blockDim.x + threadIdx.x;
    if (e >= n_edges) return;
    int slot = atomicAdd(&g_cursor[dst[e]], 1);
    g_esrc[slot] = src[e];
}

// ---------------------------------------------------------------------------
// Projection GEMM with packed f32x2 FMA.
// Block: 64 nodes x 128 cols. Thread: 8 nodes (4 pairs) x 4 cols.
// h staged TRANSPOSED [k][node] so node-pairs are contiguous (LDS.64,
// warp-uniform broadcast). w splat packed once per k, reused by 4 pairs.
// blockIdx.y selects projection.
// ---------------------------------------------------------------------------
__global__ __launch_bounds__(256) void gemm_kernel(
    const float* __restrict__ h,
    const float* __restrict__ wK,   // q  -> g_K
    const float* __restrict__ wQ,   // p  -> g_Q
    const float* __restrict__ wV,   // Wv -> g_V
    int n_nodes)
{
    __shared__ float sh_ht[32][66];   // [k within chunk][node], padded
    __shared__ float sh_w[32][128];

    const float* w    = (blockIdx.y == 0) ? wK : (blockIdx.y == 1 ? wQ : wV);
    float*       outp = (blockIdx.y == 0) ? g_K : (blockIdx.y == 1 ? g_Q : g_V);

    const int nb  = blockIdx.x * 64;
    const int tid = threadIdx.x;
    const int tx  = tid & 31;         // col group: cols tx*4 .. +3
    const int ty  = tid >> 5;         // node group: nodes ty*8 .. +7 (4 pairs)

    unsigned long long acc[4][4];     // [node-pair][col]; 0ull == (0.f, 0.f)
#pragma unroll
    for (int p = 0; p < 4; ++p)
#pragma unroll
        for (int c = 0; c < 4; ++c) acc[p][c] = 0ull;

    const float4* h4 = (const float4*)h;   // row stride 32 float4
    const float4* w4 = (const float4*)w;

    for (int kc = 0; kc < 4; ++kc) {       // K chunks of 32
        __syncthreads();
        // stage h chunk transposed: 64 nodes x 32 k (512 float4 -> scatter)
#pragma unroll
        for (int i = 0; i < 2; ++i) {
            int f    = tid + i * 256;
            int node = f >> 3, k4 = f & 7;
            int row  = nb + node;
            if (row >= n_nodes) row = n_nodes - 1;   // clamp; discarded on store
            float4 v = h4[row * 32 + kc * 8 + k4];
            sh_ht[k4 * 4 + 0][node] = v.x;
            sh_ht[k4 * 4 + 1][node] = v.y;
            sh_ht[k4 * 4 + 2][node] = v.z;
            sh_ht[k4 * 4 + 3][node] = v.w;
        }
        // stage W chunk: 32 k x 128 cols (1024 float4)
#pragma unroll
        for (int i = 0; i < 4; ++i) {
            int f = tid + i * 256;
            int r = f >> 5, c4 = f & 31;
            *(float4*)&sh_w[r][c4 * 4] = w4[(kc * 32 + r) * 32 + c4];
        }
        __syncthreads();

#pragma unroll 8
        for (int k = 0; k < 32; ++k) {
            float4 wv4 = *(const float4*)&sh_w[k][tx * 4];
            unsigned long long wp[4];
            wp[0] = pack2(wv4.x, wv4.x);
            wp[1] = pack2(wv4.y, wv4.y);
            wp[2] = pack2(wv4.z, wv4.z);
            wp[3] = pack2(wv4.w, wv4.w);
#pragma unroll
            for (int p = 0; p < 4; ++p) {
                unsigned long long hp =
                    *(const unsigned long long*)&sh_ht[k][ty * 8 + p * 2];
#pragma unroll
                for (int c = 0; c < 4; ++c)
                    acc[p][c] = ffma2(hp, wp[c], acc[p][c]);
            }
        }
    }

    // store: node-pair p covers rows nb+ty*8+2p (lo) and +1 (hi)
    float4* o4 = (float4*)outp;
#pragma unroll
    for (int p = 0; p < 4; ++p) {
        float lo0, hi0, lo1, hi1, lo2, hi2, lo3, hi3;
        unpack2(acc[p][0], lo0, hi0);
        unpack2(acc[p][1], lo1, hi1);
        unpack2(acc[p][2], lo2, hi2);
        unpack2(acc[p][3], lo3, hi3);
        int r0 = nb + ty * 8 + p * 2;
        if (r0 < n_nodes)
            o4[r0 * 32 + tx] = make_float4(lo0, lo1, lo2, lo3);
        if (r0 + 1 < n_nodes)
            o4[(r0 + 1) * 32 + tx] = make_float4(hi0, hi1, hi2, hi3);
    }
}

// ---------------------------------------------------------------------------
// Gather: one warp per dst node; registers accumulate; fused normalize.
// ---------------------------------------------------------------------------
__global__ __launch_bounds__(256) void gather_kernel(
    float* __restrict__ out, int n_nodes)
{
    const int warp = (int)((blockIdx.x * 256u + threadIdx.x) >> 5);
    if (warp >= n_nodes) return;
    const int lane = threadIdx.x & 31;
    const int node = warp;

    const float4* K4 = (const float4*)g_K;
    const float4* Q4 = (const float4*)g_Q;
    const float4* V4 = (const float4*)g_V;

    const float4 q4 = Q4[node * 32 + lane];

    const int beg = g_start[node];
    const int end = g_start[node + 1];

    float4 acc = make_float4(0.f, 0.f, 0.f, 0.f);
    float  zacc = 0.f;

    for (int base = beg; base < end; base += 32) {
        const int cnt   = min(32, end - base);
        const int myidx = (base + lane < end) ? __ldg(&g_esrc[base + lane]) : 0;

        if (cnt == 32) {
#pragma unroll 4
            for (int i = 0; i < 32; ++i) {
                int s = __shfl_sync(0xffffffffu, myidx, i);
                float4 k4 = K4[s * 32 + lane];
                float dot = k4.x * q4.x + k4.y * q4.y + k4.z * q4.z + k4.w * q4.w;
                dot += __shfl_xor_sync(0xffffffffu, dot, 1);
                dot += __shfl_xor_sync(0xffffffffu, dot, 2);
                float sc    = fminf(fmaxf(dot * 0.25f, -5.0f), 5.0f);
                float score = __expf(sc);
                float4 v4 = V4[s * 32 + lane];
                acc.x += v4.x * score;
                acc.y += v4.y * score;
                acc.z += v4.z * score;
                acc.w += v4.w * score;
                zacc  += score;
            }
        } else {
            for (int i = 0; i < cnt; ++i) {
                int s = __shfl_sync(0xffffffffu, myidx, i);
                float4 k4 = K4[s * 32 + lane];
                float dot = k4.x * q4.x + k4.y * q4.y + k4.z * q4.z + k4.w * q4.w;
                dot += __shfl_xor_sync(0xffffffffu, dot, 1);
                dot += __shfl_xor_sync(0xffffffffu, dot, 2);
                float sc    = fminf(fmaxf(dot * 0.25f, -5.0f), 5.0f);
                float score = __expf(sc);
                float4 v4 = V4[s * 32 + lane];
                acc.x += v4.x * score;
                acc.y += v4.y * score;
                acc.z += v4.z * score;
                acc.w += v4.w * score;
                zacc  += score;
            }
        }
    }

    float z   = (zacc == 0.0f) ? 0.001f : zacc;
    float inv = 1.0f / z;
    ((float4*)out)[node * 32 + lane] =
        make_float4(acc.x * inv, acc.y * inv, acc.z * inv, acc.w * inv);
}

// ---------------------------------------------------------------------------
// Side stream + events for CSR/GEMM overlap (created once at load; host-side
// objects only — no device memory allocation).
// ---------------------------------------------------------------------------
static cudaStream_t g_s2 = 0;
static cudaEvent_t  g_evFork = 0, g_evJoin = 0;
static struct SideStreamInit {
    SideStreamInit() {
        cudaStreamCreateWithFlags(&g_s2, cudaStreamNonBlocking);
        cudaEventCreateWithFlags(&g_evFork, cudaEventDisableTiming);
        cudaEventCreateWithFlags(&g_evJoin, cudaEventDisableTiming);
    }
} g_side_init;

// ---------------------------------------------------------------------------
// kernel_launch — graph-capturable, allocation-free
// Inputs: h[N*128] f32, src[E] i32, dst[E] i32,
//         p[128*128] f32, q[128*128] f32, Wv[128*128] f32
// Output: [N, 8, 16] f32
// ---------------------------------------------------------------------------
extern "C" void kernel_launch(void* const* d_in, const int* in_sizes, int n_in,
                              void* d_out, int out_size) {
    const float* h   = (const float*)d_in[0];
    const int*   src = (const int*)  d_in[1];
    const int*   dst = (const int*)  d_in[2];
    const float* p   = (const float*)d_in[3];
    const float* q   = (const float*)d_in[4];
    const float* wv  = (const float*)d_in[5];

    int n_nodes = in_sizes[0] / IN_DIM;
    int n_edges = in_sizes[1];

    float* out = (float*)d_out;

    // Fork: CSR build on side stream, concurrent with the GEMM.
    cudaEventRecord(g_evFork, 0);
    cudaStreamWaitEvent(g_s2, g_evFork, 0);

    zero_deg_kernel<<<(n_nodes + 255) / 256, 256, 0, g_s2>>>(n_nodes);
    count_kernel<<<(n_edges + 255) / 256, 256, 0, g_s2>>>(dst, n_edges);
    scan_kernel<<<1, 1024, 0, g_s2>>>(n_nodes);
    scatter_kernel<<<(n_edges + 255) / 256, 256, 0, g_s2>>>(src, dst, n_edges);
    cudaEventRecord(g_evJoin, g_s2);

    // Projections K = h@q, Q = h@p, V = h@Wv on the main stream
    {
        dim3 grid((n_nodes + 63) / 64, 3);
        gemm_kernel<<<grid, 256>>>(h, q, p, wv, n_nodes);
    }

    // Join, then per-node gather + fused normalize
    cudaStreamWaitEvent(0, g_evJoin, 0);
    {
        int blocks = (n_nodes + 7) / 8;
        gather_kernel<<<blocks, 256>>>(out, n_nodes);
    }
}